// round 8
// baseline (speedup 1.0000x reference)
#include <cuda_runtime.h>
#include <cuda_bf16.h>
#include <cstdint>
#include <math.h>

#define B_ 2
#define S_ 2048
#define DIM_ 1024
#define H_ 16
#define HD_ 64
#define HALF_ 32
#define NQKV 3072

__device__ float g_qkv[B_ * S_ * NQKV];    // fused q|k|v, row stride 3072
__device__ float g_o[B_ * S_ * DIM_];
__device__ float g_x[B_ * S_ * DIM_];      // tf32-rounded x
__device__ float g_w4[4 * DIM_ * DIM_];    // tf32-rounded wq,wk,wv (stacked) + wo

__device__ __forceinline__ unsigned f32_to_tf32(float x) {
    unsigned r;
    asm("cvt.rna.tf32.f32 %0, %1;" : "=r"(r) : "f"(x));
    return r;
}

__device__ __forceinline__ uint32_t smem_to_u32(const void* p) {
    uint32_t a;
    asm("{ .reg .u64 t; cvta.to.shared.u64 t, %1; cvt.u32.u64 %0, t; }"
        : "=r"(a) : "l"(p));
    return a;
}

#define CP_ASYNC16(dst_u32, src_ptr) \
    asm volatile("cp.async.cg.shared.global [%0], [%1], 16;" :: "r"(dst_u32), "l"(src_ptr))
#define CP_COMMIT() asm volatile("cp.async.commit_group;" ::: "memory")
#define CP_WAIT(n) asm volatile("cp.async.wait_group %0;" :: "n"(n) : "memory")

#define MMA_TF32(acc, a0, a1, a2, a3, b0, b1)                                  \
    asm volatile(                                                              \
        "mma.sync.aligned.m16n8k8.row.col.f32.tf32.tf32.f32 "                  \
        "{%0,%1,%2,%3}, {%4,%5,%6,%7}, {%8,%9}, {%0,%1,%2,%3};"                \
        : "+f"(acc[0]), "+f"(acc[1]), "+f"(acc[2]), "+f"(acc[3])               \
        : "r"(a0), "r"(a1), "r"(a2), "r"(a3), "r"(b0), "r"(b1))

#define LDMATRIX_X4(r0, r1, r2, r3, addr)                                      \
    asm volatile("ldmatrix.sync.aligned.m8n8.x4.shared.b16 {%0,%1,%2,%3}, [%4];" \
                 : "=r"(r0), "=r"(r1), "=r"(r2), "=r"(r3) : "r"(addr))
#define LDMATRIX_X2(r0, r1, addr)                                              \
    asm volatile("ldmatrix.sync.aligned.m8n8.x2.shared.b16 {%0,%1}, [%2];"     \
                 : "=r"(r0), "=r"(r1) : "r"(addr))

// ---------------------------------------------------------------------------
// tf32 rounding pre-passes
// ---------------------------------------------------------------------------
__global__ void round_tf32_kernel(const float* __restrict__ src,
                                  float* __restrict__ dst, int n4) {
    int i = blockIdx.x * blockDim.x + threadIdx.x;
    if (i >= n4) return;
    float4 v = ((const float4*)src)[i];
    ((float4*)dst)[i] = make_float4(
        __uint_as_float(f32_to_tf32(v.x)), __uint_as_float(f32_to_tf32(v.y)),
        __uint_as_float(f32_to_tf32(v.z)), __uint_as_float(f32_to_tf32(v.w)));
}

__global__ void round_w4_kernel(const float* __restrict__ w0,
                                const float* __restrict__ w1,
                                const float* __restrict__ w2,
                                const float* __restrict__ w3,
                                float* __restrict__ dst) {
    const int nw4 = (DIM_ * DIM_) / 4;   // float4s per weight
    int i = blockIdx.x * blockDim.x + threadIdx.x;
    if (i >= 4 * nw4) return;
    int seg = i / nw4;
    int off = i - seg * nw4;
    const float* src = (seg == 0) ? w0 : (seg == 1) ? w1 : (seg == 2) ? w2 : w3;
    float4 v = ((const float4*)src)[off];
    ((float4*)dst)[i] = make_float4(
        __uint_as_float(f32_to_tf32(v.x)), __uint_as_float(f32_to_tf32(v.y)),
        __uint_as_float(f32_to_tf32(v.z)), __uint_as_float(f32_to_tf32(v.w)));
}

// ---------------------------------------------------------------------------
// TF32 mma.sync GEMM, cp.async double-buffered, ldmatrix fragment loads,
// optional fused RoPE epilogue. C[M,NS] = A[M,K] @ B[NS,K]^T.
// Block 128x128, BK=32, 256 threads = 8 warps (2x4), warp tile 64x32.
// ---------------------------------------------------------------------------
#define BKG 32
#define LDT 36
#define TILE_FLOATS (128 * LDT)
#define STAGE_FLOATS (2 * TILE_FLOATS)
#define GEMM_SMEM (2 * STAGE_FLOATS * 4)   // 73728 B

__global__ void __launch_bounds__(256, 2) gemm_tf32p(const float* __restrict__ A,
                                                     const float* __restrict__ Bm,
                                                     float* __restrict__ C,
                                                     int NS, int K, int mode,
                                                     const float* __restrict__ cosb,
                                                     const float* __restrict__ sinb) {
    extern __shared__ float sm[];
    const uint32_t smem_base = smem_to_u32(sm);

    const int tid = threadIdx.x;
    const int wid = tid >> 5;
    const int lane = tid & 31;
    const int gid = lane >> 2;
    const int tig = lane & 3;
    const int warp_m = wid >> 2;
    const int warp_n = wid & 3;
    const int bx = blockIdx.x;
    const int by = blockIdx.y;

    const float* Ab = A + (size_t)(by * 128) * K;
    const float* Bb = Bm + (size_t)(bx * 128) * K;

    const int crow = tid >> 3;
    const int cc4 = tid & 7;

    auto issue_copy = [&](int c, int s) {
        uint32_t abase = smem_base + (uint32_t)(s * STAGE_FLOATS) * 4;
        uint32_t bbase = abase + (uint32_t)TILE_FLOATS * 4;
        const float* Ap = Ab + c * BKG;
        const float* Bp = Bb + c * BKG;
#pragma unroll
        for (int i = 0; i < 4; i++) {
            int row = crow + i * 32;
            uint32_t off = (uint32_t)(row * LDT + cc4 * 4) * 4;
            CP_ASYNC16(abase + off, Ap + (size_t)row * K + cc4 * 4);
            CP_ASYNC16(bbase + off, Bp + (size_t)row * K + cc4 * 4);
        }
    };

    // ldmatrix lane-address offsets (element units within a tile)
    // A x4 tiles: t0=(rows 0-7, col 0), t1=(rows 8-15, col 0),
    //             t2=(rows 0-7, col 4), t3=(rows 8-15, col 4)
    const int a_tile = lane >> 3;
    const int a_r = lane & 7;
    const int a_row_off = ((a_tile & 1) ? 8 : 0) + a_r;
    const int a_col_off = (a_tile >= 2) ? 4 : 0;
    // B x2 tiles (lanes 0-15): t0=(rows 0-7, col 0), t1=(rows 0-7, col 4)
    const int b_tile = (lane >> 3) & 1;
    const int b_r = lane & 7;

    float acc[4][4][4];
#pragma unroll
    for (int mi = 0; mi < 4; mi++)
#pragma unroll
        for (int ni = 0; ni < 4; ni++)
#pragma unroll
            for (int c = 0; c < 4; c++) acc[mi][ni][c] = 0.0f;

    const int nchunks = K / BKG;
    issue_copy(0, 0);
    CP_COMMIT();

#pragma unroll 1
    for (int c = 0; c < nchunks; c++) {
        const int s = c & 1;
        if (c + 1 < nchunks) {
            issue_copy(c + 1, s ^ 1);
            CP_COMMIT();
            CP_WAIT(1);
        } else {
            CP_WAIT(0);
        }
        __syncthreads();

        const uint32_t As_u = smem_base + (uint32_t)(s * STAGE_FLOATS) * 4;
        const uint32_t Bs_u = As_u + (uint32_t)TILE_FLOATS * 4;

        // Per-warp fragment base addresses (bytes)
        const uint32_t a_base =
            As_u + (uint32_t)((warp_m * 64 + a_row_off) * LDT + a_col_off) * 4;
        const uint32_t b_base =
            Bs_u + (uint32_t)((warp_n * 32 + b_r) * LDT + (b_tile ? 4 : 0)) * 4;

#pragma unroll
        for (int ks = 0; ks < BKG; ks += 8) {
            unsigned a[4][4], b[4][2];
#pragma unroll
            for (int mi = 0; mi < 4; mi++) {
                uint32_t ad = a_base + (uint32_t)(mi * 16 * LDT + ks) * 4;
                LDMATRIX_X4(a[mi][0], a[mi][1], a[mi][2], a[mi][3], ad);
            }
#pragma unroll
            for (int ni = 0; ni < 4; ni++) {
                uint32_t bd = b_base + (uint32_t)(ni * 8 * LDT + ks) * 4;
                LDMATRIX_X2(b[ni][0], b[ni][1], bd);
            }
#pragma unroll
            for (int mi = 0; mi < 4; mi++)
#pragma unroll
                for (int ni = 0; ni < 4; ni++)
                    MMA_TF32(acc[mi][ni], a[mi][0], a[mi][1], a[mi][2], a[mi][3],
                             b[ni][0], b[ni][1]);
        }
        __syncthreads();
    }

#pragma unroll
    for (int mi = 0; mi < 4; mi++) {
#pragma unroll
        for (int ni = 0; ni < 4; ni++) {
            int rA = by * 128 + warp_m * 64 + mi * 16 + gid;
            int rB = rA + 8;
            int cc = bx * 128 + warp_n * 32 + ni * 8 + 2 * tig;
            float e0 = acc[mi][ni][0], o0 = acc[mi][ni][1];
            float e1 = acc[mi][ni][2], o1 = acc[mi][ni][3];
            if (mode && cc < 2048) {
                int p = (cc & 63) >> 1;
                float cA = cosb[(rA & (S_ - 1)) * HALF_ + p];
                float sA = sinb[(rA & (S_ - 1)) * HALF_ + p];
                float cB = cosb[(rB & (S_ - 1)) * HALF_ + p];
                float sB = sinb[(rB & (S_ - 1)) * HALF_ + p];
                float t0 = e0 * cA - o0 * sA, t1 = e0 * sA + o0 * cA;
                e0 = t0; o0 = t1;
                float t2 = e1 * cB - o1 * sB, t3 = e1 * sB + o1 * cB;
                e1 = t2; o1 = t3;
            }
            *(float2*)(C + (size_t)rA * NS + cc) = make_float2(e0, o0);
            *(float2*)(C + (size_t)rB * NS + cc) = make_float2(e1, o1);
        }
    }
}

// ---------------------------------------------------------------------------
// Flash attention with warp-level tf32 mma (reads fused qkv buffer).
// ---------------------------------------------------------------------------
#define FLDT 68

__global__ void __launch_bounds__(256) flash_mma(const float* __restrict__ QKV,
                                                 float* __restrict__ O) {
    __shared__ unsigned sm[128 * FLDT];
    unsigned* Ks = sm;
    unsigned* Vs = sm + 64 * FLDT;

    const int tid = threadIdx.x;
    const int wid = tid >> 5;
    const int lane = tid & 31;
    const int gid = lane >> 2;
    const int tig = lane & 3;
    const int bx = blockIdx.x;
    const int h = blockIdx.y;
    const int b = blockIdx.z;
    const int qbase = bx * 128;

#pragma unroll
    for (int i = 0; i < 8; i++) {
        int lin = tid + i * 256;
        int row = lin >> 4;
        int c4 = lin & 15;
        float4 v = *(const float4*)(QKV + (size_t)(b * S_ + qbase + row) * NQKV + h * HD_ + c4 * 4);
        unsigned* d = &sm[row * FLDT + c4 * 4];
        d[0] = f32_to_tf32(v.x * 0.125f); d[1] = f32_to_tf32(v.y * 0.125f);
        d[2] = f32_to_tf32(v.z * 0.125f); d[3] = f32_to_tf32(v.w * 0.125f);
    }
    __syncthreads();

    const int r0 = wid * 16;
    unsigned qf[8][4];
#pragma unroll
    for (int ks = 0; ks < 8; ks++) {
        int c = ks * 8 + tig;
        qf[ks][0] = sm[(r0 + gid) * FLDT + c];
        qf[ks][1] = sm[(r0 + gid + 8) * FLDT + c];
        qf[ks][2] = sm[(r0 + gid) * FLDT + c + 4];
        qf[ks][3] = sm[(r0 + gid + 8) * FLDT + c + 4];
    }

    float oacc[8][4];
#pragma unroll
    for (int nd = 0; nd < 8; nd++)
#pragma unroll
        for (int c = 0; c < 4; c++) oacc[nd][c] = 0.0f;
    float m0 = -1e30f, m1 = -1e30f, l0 = 0.0f, l1 = 0.0f;

    const int r0g = qbase + r0;
    const int kend = qbase + 128;
    const int srcA = (lane & ~3) | (tig >> 1);
    const int srcB = srcA + 2;
    const int par = tig & 1;

    for (int kt = 0; kt < kend; kt += 64) {
        __syncthreads();
#pragma unroll
        for (int i = 0; i < 4; i++) {
            int lin = tid + i * 256;
            int row = lin >> 4;
            int c4 = lin & 15;
            size_t g = (size_t)(b * S_ + kt + row) * NQKV + h * HD_ + c4 * 4;
            float4 kv = *(const float4*)(QKV + g + 1024);
            unsigned* d = &Ks[row * FLDT + c4 * 4];
            d[0] = f32_to_tf32(kv.x); d[1] = f32_to_tf32(kv.y);
            d[2] = f32_to_tf32(kv.z); d[3] = f32_to_tf32(kv.w);
            float4 vv = *(const float4*)(QKV + g + 2048);
            Vs[(c4 * 4 + 0) * FLDT + row] = f32_to_tf32(vv.x);
            Vs[(c4 * 4 + 1) * FLDT + row] = f32_to_tf32(vv.y);
            Vs[(c4 * 4 + 2) * FLDT + row] = f32_to_tf32(vv.z);
            Vs[(c4 * 4 + 3) * FLDT + row] = f32_to_tf32(vv.w);
        }
        __syncthreads();

        if (kt > r0g + 15) continue;

        float sf[8][4];
#pragma unroll
        for (int nt = 0; nt < 8; nt++) {
            sf[nt][0] = 0.0f; sf[nt][1] = 0.0f; sf[nt][2] = 0.0f; sf[nt][3] = 0.0f;
#pragma unroll
            for (int ks = 0; ks < 8; ks++) {
                unsigned b0 = Ks[(nt * 8 + gid) * FLDT + ks * 8 + tig];
                unsigned b1 = Ks[(nt * 8 + gid) * FLDT + ks * 8 + tig + 4];
                MMA_TF32(sf[nt], qf[ks][0], qf[ks][1], qf[ks][2], qf[ks][3], b0, b1);
            }
        }

        if (kt + 63 > r0g) {
            int rA = r0g + gid;
            int rB = rA + 8;
#pragma unroll
            for (int nt = 0; nt < 8; nt++) {
                int colb = kt + nt * 8 + 2 * tig;
                if (colb > rA) sf[nt][0] = -1e30f;
                if (colb + 1 > rA) sf[nt][1] = -1e30f;
                if (colb > rB) sf[nt][2] = -1e30f;
                if (colb + 1 > rB) sf[nt][3] = -1e30f;
            }
        }

        float mx0 = m0, mx1 = m1;
#pragma unroll
        for (int nt = 0; nt < 8; nt++) {
            mx0 = fmaxf(mx0, fmaxf(sf[nt][0], sf[nt][1]));
            mx1 = fmaxf(mx1, fmaxf(sf[nt][2], sf[nt][3]));
        }
        mx0 = fmaxf(mx0, __shfl_xor_sync(0xffffffffu, mx0, 1));
        mx0 = fmaxf(mx0, __shfl_xor_sync(0xffffffffu, mx0, 2));
        mx1 = fmaxf(mx1, __shfl_xor_sync(0xffffffffu, mx1, 1));
        mx1 = fmaxf(mx1, __shfl_xor_sync(0xffffffffu, mx1, 2));

        float corr0 = __expf(m0 - mx0);
        float corr1 = __expf(m1 - mx1);
        float rs0 = 0.0f, rs1 = 0.0f;
#pragma unroll
        for (int nt = 0; nt < 8; nt++) {
            sf[nt][0] = __expf(sf[nt][0] - mx0);
            sf[nt][1] = __expf(sf[nt][1] - mx0);
            sf[nt][2] = __expf(sf[nt][2] - mx1);
            sf[nt][3] = __expf(sf[nt][3] - mx1);
            rs0 += sf[nt][0] + sf[nt][1];
            rs1 += sf[nt][2] + sf[nt][3];
        }
        rs0 += __shfl_xor_sync(0xffffffffu, rs0, 1);
        rs0 += __shfl_xor_sync(0xffffffffu, rs0, 2);
        rs1 += __shfl_xor_sync(0xffffffffu, rs1, 1);
        rs1 += __shfl_xor_sync(0xffffffffu, rs1, 2);
        l0 = l0 * corr0 + rs0;
        l1 = l1 * corr1 + rs1;
        m0 = mx0; m1 = mx1;
#pragma unroll
        for (int nd = 0; nd < 8; nd++) {
            oacc[nd][0] *= corr0; oacc[nd][1] *= corr0;
            oacc[nd][2] *= corr1; oacc[nd][3] *= corr1;
        }

#pragma unroll
        for (int ki = 0; ki < 8; ki++) {
            float xA0 = __shfl_sync(0xffffffffu, sf[ki][0], srcA);
            float xA1 = __shfl_sync(0xffffffffu, sf[ki][1], srcA);
            float xA2 = __shfl_sync(0xffffffffu, sf[ki][2], srcA);
            float xA3 = __shfl_sync(0xffffffffu, sf[ki][3], srcA);
            float xB0 = __shfl_sync(0xffffffffu, sf[ki][0], srcB);
            float xB1 = __shfl_sync(0xffffffffu, sf[ki][1], srcB);
            float xB2 = __shfl_sync(0xffffffffu, sf[ki][2], srcB);
            float xB3 = __shfl_sync(0xffffffffu, sf[ki][3], srcB);
            unsigned a0 = f32_to_tf32(par ? xA1 : xA0);
            unsigned a1 = f32_to_tf32(par ? xA3 : xA2);
            unsigned a2 = f32_to_tf32(par ? xB1 : xB0);
            unsigned a3 = f32_to_tf32(par ? xB3 : xB2);
#pragma unroll
            for (int nd = 0; nd < 8; nd++) {
                unsigned b0 = Vs[(nd * 8 + gid) * FLDT + ki * 8 + tig];
                unsigned b1 = Vs[(nd * 8 + gid) * FLDT + ki * 8 + tig + 4];
                MMA_TF32(oacc[nd], a0, a1, a2, a3, b0, b1);
            }
        }
    }

    float inv0 = 1.0f / l0;
    float inv1 = 1.0f / l1;
    int rA = r0g + gid;
    int rB = rA + 8;
#pragma unroll
    for (int nd = 0; nd < 8; nd++) {
        int col = nd * 8 + 2 * tig;
        *(float2*)(O + ((size_t)(b * S_ + rA) * H_ + h) * HD_ + col) = make_float2(
            __uint_as_float(f32_to_tf32(oacc[nd][0] * inv0)),
            __uint_as_float(f32_to_tf32(oacc[nd][1] * inv0)));
        *(float2*)(O + ((size_t)(b * S_ + rB) * H_ + h) * HD_ + col) = make_float2(
            __uint_as_float(f32_to_tf32(oacc[nd][2] * inv1)),
            __uint_as_float(f32_to_tf32(oacc[nd][3] * inv1)));
    }
}

// ---------------------------------------------------------------------------
// Launch: 5 launches total, so ncu (-s 5, captures launch #5) profiles the
// final GEMM.
// ---------------------------------------------------------------------------
extern "C" void kernel_launch(void* const* d_in, const int* in_sizes, int n_in,
                              void* d_out, int out_size) {
    const float* x = (const float*)d_in[0];
    const float* cosb = (const float*)d_in[1];
    const float* sinb = (const float*)d_in[2];
    const float* wq = (const float*)d_in[4];
    const float* wk = (const float*)d_in[5];
    const float* wv = (const float*)d_in[6];
    const float* wo = (const float*)d_in[7];
    float* out = (float*)d_out;

    float *qkv, *o, *xr, *w4;
    cudaGetSymbolAddress((void**)&qkv, g_qkv);
    cudaGetSymbolAddress((void**)&o, g_o);
    cudaGetSymbolAddress((void**)&xr, g_x);
    cudaGetSymbolAddress((void**)&w4, g_w4);
    float* wor = w4 + 3 * DIM_ * DIM_;

    const int K = DIM_;

    cudaFuncSetAttribute(gemm_tf32p, cudaFuncAttributeMaxDynamicSharedMemorySize,
                         GEMM_SMEM);

    // 1: round x, 2: round all 4 weights
    int nx4 = (B_ * S_ * DIM_) / 4;
    int nw4all = DIM_ * DIM_;          // 4 * (DIM*DIM/4)
    round_tf32_kernel<<<nx4 / 256, 256>>>(x, xr, nx4);
    round_w4_kernel<<<nw4all / 256, 256>>>(wq, wk, wv, wo, w4);

    // 3: fused QKV GEMM + RoPE epilogue
    dim3 qkv_grid(NQKV / 128, (B_ * S_) / 128);   // (24, 32)
    gemm_tf32p<<<qkv_grid, 256, GEMM_SMEM>>>(xr, w4, qkv, NQKV, K, 1, cosb, sinb);

    // 4: flash attention
    dim3 attn_grid(S_ / 128, H_, B_);
    flash_mma<<<attn_grid, 256>>>(qkv, o);

    // 5: output GEMM (profiled launch)
    dim3 out_grid(DIM_ / 128, (B_ * S_) / 128);   // (8, 32)
    gemm_tf32p<<<out_grid, 256, GEMM_SMEM>>>(o, wor, out, DIM_, K, 0, cosb, sinb);
}

// round 9
// speedup vs baseline: 1.5731x; 1.5731x over previous
#include <cuda_runtime.h>
#include <cuda_bf16.h>
#include <cstdint>
#include <math.h>

#define B_ 2
#define S_ 2048
#define DIM_ 1024
#define H_ 16
#define HD_ 64
#define HALF_ 32
#define NQKV 3072

__device__ float g_qkv[B_ * S_ * NQKV];    // fused q|k|v (tf32-rounded, q pre-scaled)
__device__ float g_o[B_ * S_ * DIM_];
__device__ float g_x[B_ * S_ * DIM_];      // tf32-rounded x
__device__ float g_w4[4 * DIM_ * DIM_];    // tf32-rounded wq,wk,wv (stacked) + wo

__device__ __forceinline__ unsigned f32_to_tf32(float x) {
    unsigned r;
    asm("cvt.rna.tf32.f32 %0, %1;" : "=r"(r) : "f"(x));
    return r;
}
__device__ __forceinline__ float round_tf32f(float x) {
    return __uint_as_float(f32_to_tf32(x));
}

__device__ __forceinline__ uint32_t smem_to_u32(const void* p) {
    uint32_t a;
    asm("{ .reg .u64 t; cvta.to.shared.u64 t, %1; cvt.u32.u64 %0, t; }"
        : "=r"(a) : "l"(p));
    return a;
}

#define CP_ASYNC16(dst_u32, src_ptr) \
    asm volatile("cp.async.cg.shared.global [%0], [%1], 16;" :: "r"(dst_u32), "l"(src_ptr))
#define CP_COMMIT() asm volatile("cp.async.commit_group;" ::: "memory")
#define CP_WAIT(n) asm volatile("cp.async.wait_group %0;" :: "n"(n) : "memory")

#define MMA_TF32(acc, a0, a1, a2, a3, b0, b1)                                  \
    asm volatile(                                                              \
        "mma.sync.aligned.m16n8k8.row.col.f32.tf32.tf32.f32 "                  \
        "{%0,%1,%2,%3}, {%4,%5,%6,%7}, {%8,%9}, {%0,%1,%2,%3};"                \
        : "+f"(acc[0]), "+f"(acc[1]), "+f"(acc[2]), "+f"(acc[3])               \
        : "r"(a0), "r"(a1), "r"(a2), "r"(a3), "r"(b0), "r"(b1))

// ---------------------------------------------------------------------------
// tf32 rounding pre-passes
// ---------------------------------------------------------------------------
__global__ void round_tf32_kernel(const float* __restrict__ src,
                                  float* __restrict__ dst, int n4) {
    int i = blockIdx.x * blockDim.x + threadIdx.x;
    if (i >= n4) return;
    float4 v = ((const float4*)src)[i];
    ((float4*)dst)[i] = make_float4(round_tf32f(v.x), round_tf32f(v.y),
                                    round_tf32f(v.z), round_tf32f(v.w));
}

__global__ void round_w4_kernel(const float* __restrict__ w0,
                                const float* __restrict__ w1,
                                const float* __restrict__ w2,
                                const float* __restrict__ w3,
                                float* __restrict__ dst) {
    const int nw4 = (DIM_ * DIM_) / 4;
    int i = blockIdx.x * blockDim.x + threadIdx.x;
    if (i >= 4 * nw4) return;
    int seg = i / nw4;
    int off = i - seg * nw4;
    const float* src = (seg == 0) ? w0 : (seg == 1) ? w1 : (seg == 2) ? w2 : w3;
    float4 v = ((const float4*)src)[off];
    ((float4*)dst)[i] = make_float4(round_tf32f(v.x), round_tf32f(v.y),
                                    round_tf32f(v.z), round_tf32f(v.w));
}

// ---------------------------------------------------------------------------
// TF32 mma.sync GEMM (R7 configuration: scalar fragment LDS), cp.async
// double-buffered. mode=1: RoPE on cols<2048, then round all outputs to tf32
// and pre-scale q cols (<1024) by 0.125 (feeds flash with ready operands).
// ---------------------------------------------------------------------------
#define BKG 32
#define LDT 36
#define TILE_FLOATS (128 * LDT)
#define STAGE_FLOATS (2 * TILE_FLOATS)
#define GEMM_SMEM (2 * STAGE_FLOATS * 4)   // 73728 B

__global__ void __launch_bounds__(256, 2) gemm_tf32p(const float* __restrict__ A,
                                                     const float* __restrict__ Bm,
                                                     float* __restrict__ C,
                                                     int NS, int K, int mode,
                                                     const float* __restrict__ cosb,
                                                     const float* __restrict__ sinb) {
    extern __shared__ float sm[];
    const uint32_t smem_base = smem_to_u32(sm);

    const int tid = threadIdx.x;
    const int wid = tid >> 5;
    const int lane = tid & 31;
    const int gid = lane >> 2;
    const int tig = lane & 3;
    const int warp_m = wid >> 2;
    const int warp_n = wid & 3;
    const int bx = blockIdx.x;
    const int by = blockIdx.y;

    const float* Ab = A + (size_t)(by * 128) * K;
    const float* Bb = Bm + (size_t)(bx * 128) * K;

    const int crow = tid >> 3;
    const int cc4 = tid & 7;

    auto issue_copy = [&](int c, int s) {
        uint32_t abase = smem_base + (uint32_t)(s * STAGE_FLOATS) * 4;
        uint32_t bbase = abase + (uint32_t)TILE_FLOATS * 4;
        const float* Ap = Ab + c * BKG;
        const float* Bp = Bb + c * BKG;
#pragma unroll
        for (int i = 0; i < 4; i++) {
            int row = crow + i * 32;
            uint32_t off = (uint32_t)(row * LDT + cc4 * 4) * 4;
            CP_ASYNC16(abase + off, Ap + (size_t)row * K + cc4 * 4);
            CP_ASYNC16(bbase + off, Bp + (size_t)row * K + cc4 * 4);
        }
    };

    float acc[4][4][4];
#pragma unroll
    for (int mi = 0; mi < 4; mi++)
#pragma unroll
        for (int ni = 0; ni < 4; ni++)
#pragma unroll
            for (int c = 0; c < 4; c++) acc[mi][ni][c] = 0.0f;

    const int nchunks = K / BKG;
    issue_copy(0, 0);
    CP_COMMIT();

#pragma unroll 1
    for (int c = 0; c < nchunks; c++) {
        const int s = c & 1;
        if (c + 1 < nchunks) {
            issue_copy(c + 1, s ^ 1);
            CP_COMMIT();
            CP_WAIT(1);
        } else {
            CP_WAIT(0);
        }
        __syncthreads();

        const unsigned* As = (const unsigned*)(sm + s * STAGE_FLOATS);
        const unsigned* Bs = (const unsigned*)(sm + s * STAGE_FLOATS + TILE_FLOATS);

#pragma unroll
        for (int ks = 0; ks < BKG; ks += 8) {
            unsigned a[4][4], b[4][2];
#pragma unroll
            for (int mi = 0; mi < 4; mi++) {
                int r = warp_m * 64 + mi * 16 + gid;
                int cc = ks + tig;
                a[mi][0] = As[r * LDT + cc];
                a[mi][1] = As[(r + 8) * LDT + cc];
                a[mi][2] = As[r * LDT + cc + 4];
                a[mi][3] = As[(r + 8) * LDT + cc + 4];
            }
#pragma unroll
            for (int ni = 0; ni < 4; ni++) {
                int n = warp_n * 32 + ni * 8 + gid;
                int cc = ks + tig;
                b[ni][0] = Bs[n * LDT + cc];
                b[ni][1] = Bs[n * LDT + cc + 4];
            }
#pragma unroll
            for (int mi = 0; mi < 4; mi++)
#pragma unroll
                for (int ni = 0; ni < 4; ni++)
                    MMA_TF32(acc[mi][ni], a[mi][0], a[mi][1], a[mi][2], a[mi][3],
                             b[ni][0], b[ni][1]);
        }
        __syncthreads();
    }

#pragma unroll
    for (int mi = 0; mi < 4; mi++) {
#pragma unroll
        for (int ni = 0; ni < 4; ni++) {
            int rA = by * 128 + warp_m * 64 + mi * 16 + gid;
            int rB = rA + 8;
            int cc = bx * 128 + warp_n * 32 + ni * 8 + 2 * tig;
            float e0 = acc[mi][ni][0], o0 = acc[mi][ni][1];
            float e1 = acc[mi][ni][2], o1 = acc[mi][ni][3];
            if (mode) {
                if (cc < 2048) {
                    int p = (cc & 63) >> 1;
                    float cA = cosb[(rA & (S_ - 1)) * HALF_ + p];
                    float sA = sinb[(rA & (S_ - 1)) * HALF_ + p];
                    float cB = cosb[(rB & (S_ - 1)) * HALF_ + p];
                    float sB = sinb[(rB & (S_ - 1)) * HALF_ + p];
                    float t0 = e0 * cA - o0 * sA, t1 = e0 * sA + o0 * cA;
                    e0 = t0; o0 = t1;
                    float t2 = e1 * cB - o1 * sB, t3 = e1 * sB + o1 * cB;
                    e1 = t2; o1 = t3;
                }
                float sc = (cc < 1024) ? 0.125f : 1.0f;
                e0 = round_tf32f(e0 * sc); o0 = round_tf32f(o0 * sc);
                e1 = round_tf32f(e1 * sc); o1 = round_tf32f(o1 * sc);
            }
            *(float2*)(C + (size_t)rA * NS + cc) = make_float2(e0, o0);
            *(float2*)(C + (size_t)rB * NS + cc) = make_float2(e1, o1);
        }
    }
}

// ---------------------------------------------------------------------------
// Flash attention, tf32 mma. Operands pre-rounded (and q pre-scaled) by the
// QKV GEMM epilogue: loads are raw copies. V kept in natural [key][d] layout.
// ---------------------------------------------------------------------------
#define FLDT 68

__global__ void __launch_bounds__(256, 2) flash_mma(const float* __restrict__ QKV,
                                                    float* __restrict__ O) {
    __shared__ float sm[128 * FLDT];
    float* Ks = sm;                 // [key][d]
    float* Vs = sm + 64 * FLDT;     // [key][d]  (natural layout)

    const int tid = threadIdx.x;
    const int wid = tid >> 5;
    const int lane = tid & 31;
    const int gid = lane >> 2;
    const int tig = lane & 3;
    const int bx = blockIdx.x;
    const int h = blockIdx.y;
    const int b = blockIdx.z;
    const int qbase = bx * 128;

    // Stage Q tile (already scaled+rounded) and pull fragments
#pragma unroll
    for (int i = 0; i < 8; i++) {
        int lin = tid + i * 256;
        int row = lin >> 4;
        int c4 = lin & 15;
        *(float4*)(&sm[row * FLDT + c4 * 4]) =
            *(const float4*)(QKV + (size_t)(b * S_ + qbase + row) * NQKV + h * HD_ + c4 * 4);
    }
    __syncthreads();

    const int r0 = wid * 16;
    unsigned qf[8][4];
#pragma unroll
    for (int ks = 0; ks < 8; ks++) {
        int c = ks * 8 + tig;
        qf[ks][0] = __float_as_uint(sm[(r0 + gid) * FLDT + c]);
        qf[ks][1] = __float_as_uint(sm[(r0 + gid + 8) * FLDT + c]);
        qf[ks][2] = __float_as_uint(sm[(r0 + gid) * FLDT + c + 4]);
        qf[ks][3] = __float_as_uint(sm[(r0 + gid + 8) * FLDT + c + 4]);
    }

    float oacc[8][4];
#pragma unroll
    for (int nd = 0; nd < 8; nd++)
#pragma unroll
        for (int c = 0; c < 4; c++) oacc[nd][c] = 0.0f;
    float m0 = -1e30f, m1 = -1e30f, l0 = 0.0f, l1 = 0.0f;

    const int r0g = qbase + r0;
    const int kend = qbase + 128;
    const int srcA = (lane & ~3) | (tig >> 1);
    const int srcB = srcA + 2;
    const int par = tig & 1;

    for (int kt = 0; kt < kend; kt += 64) {
        __syncthreads();
        // Cooperative raw copies: K and V rows (both [key][d], conflict-free)
#pragma unroll
        for (int i = 0; i < 4; i++) {
            int lin = tid + i * 256;
            int row = lin >> 4;
            int c4 = lin & 15;
            size_t g = (size_t)(b * S_ + kt + row) * NQKV + h * HD_ + c4 * 4;
            *(float4*)(&Ks[row * FLDT + c4 * 4]) = *(const float4*)(QKV + g + 1024);
            *(float4*)(&Vs[row * FLDT + c4 * 4]) = *(const float4*)(QKV + g + 2048);
        }
        __syncthreads();

        if (kt > r0g + 15) continue;

        // S = Q @ K^T
        float sf[8][4];
#pragma unroll
        for (int nt = 0; nt < 8; nt++) {
            sf[nt][0] = 0.0f; sf[nt][1] = 0.0f; sf[nt][2] = 0.0f; sf[nt][3] = 0.0f;
#pragma unroll
            for (int ks = 0; ks < 8; ks++) {
                unsigned b0 = __float_as_uint(Ks[(nt * 8 + gid) * FLDT + ks * 8 + tig]);
                unsigned b1 = __float_as_uint(Ks[(nt * 8 + gid) * FLDT + ks * 8 + tig + 4]);
                MMA_TF32(sf[nt], qf[ks][0], qf[ks][1], qf[ks][2], qf[ks][3], b0, b1);
            }
        }

        if (kt + 63 > r0g) {
            int rA = r0g + gid;
            int rB = rA + 8;
#pragma unroll
            for (int nt = 0; nt < 8; nt++) {
                int colb = kt + nt * 8 + 2 * tig;
                if (colb > rA) sf[nt][0] = -1e30f;
                if (colb + 1 > rA) sf[nt][1] = -1e30f;
                if (colb > rB) sf[nt][2] = -1e30f;
                if (colb + 1 > rB) sf[nt][3] = -1e30f;
            }
        }

        float mx0 = m0, mx1 = m1;
#pragma unroll
        for (int nt = 0; nt < 8; nt++) {
            mx0 = fmaxf(mx0, fmaxf(sf[nt][0], sf[nt][1]));
            mx1 = fmaxf(mx1, fmaxf(sf[nt][2], sf[nt][3]));
        }
        mx0 = fmaxf(mx0, __shfl_xor_sync(0xffffffffu, mx0, 1));
        mx0 = fmaxf(mx0, __shfl_xor_sync(0xffffffffu, mx0, 2));
        mx1 = fmaxf(mx1, __shfl_xor_sync(0xffffffffu, mx1, 1));
        mx1 = fmaxf(mx1, __shfl_xor_sync(0xffffffffu, mx1, 2));

        float corr0 = __expf(m0 - mx0);
        float corr1 = __expf(m1 - mx1);
        float rs0 = 0.0f, rs1 = 0.0f;
#pragma unroll
        for (int nt = 0; nt < 8; nt++) {
            sf[nt][0] = __expf(sf[nt][0] - mx0);
            sf[nt][1] = __expf(sf[nt][1] - mx0);
            sf[nt][2] = __expf(sf[nt][2] - mx1);
            sf[nt][3] = __expf(sf[nt][3] - mx1);
            rs0 += sf[nt][0] + sf[nt][1];
            rs1 += sf[nt][2] + sf[nt][3];
        }
        rs0 += __shfl_xor_sync(0xffffffffu, rs0, 1);
        rs0 += __shfl_xor_sync(0xffffffffu, rs0, 2);
        rs1 += __shfl_xor_sync(0xffffffffu, rs1, 1);
        rs1 += __shfl_xor_sync(0xffffffffu, rs1, 2);
        l0 = l0 * corr0 + rs0;
        l1 = l1 * corr1 + rs1;
        m0 = mx0; m1 = mx1;
#pragma unroll
        for (int nd = 0; nd < 8; nd++) {
            oacc[nd][0] *= corr0; oacc[nd][1] *= corr0;
            oacc[nd][2] *= corr1; oacc[nd][3] *= corr1;
        }

        // O += P @ V ; P C-frag -> A-frag via shuffles, V read from [key][d]
#pragma unroll
        for (int ki = 0; ki < 8; ki++) {
            float xA0 = __shfl_sync(0xffffffffu, sf[ki][0], srcA);
            float xA1 = __shfl_sync(0xffffffffu, sf[ki][1], srcA);
            float xA2 = __shfl_sync(0xffffffffu, sf[ki][2], srcA);
            float xA3 = __shfl_sync(0xffffffffu, sf[ki][3], srcA);
            float xB0 = __shfl_sync(0xffffffffu, sf[ki][0], srcB);
            float xB1 = __shfl_sync(0xffffffffu, sf[ki][1], srcB);
            float xB2 = __shfl_sync(0xffffffffu, sf[ki][2], srcB);
            float xB3 = __shfl_sync(0xffffffffu, sf[ki][3], srcB);
            unsigned a0 = f32_to_tf32(par ? xA1 : xA0);
            unsigned a1 = f32_to_tf32(par ? xA3 : xA2);
            unsigned a2 = f32_to_tf32(par ? xB1 : xB0);
            unsigned a3 = f32_to_tf32(par ? xB3 : xB2);
#pragma unroll
            for (int nd = 0; nd < 8; nd++) {
                unsigned b0 = __float_as_uint(Vs[(ki * 8 + tig) * FLDT + nd * 8 + gid]);
                unsigned b1 = __float_as_uint(Vs[(ki * 8 + tig + 4) * FLDT + nd * 8 + gid]);
                MMA_TF32(oacc[nd], a0, a1, a2, a3, b0, b1);
            }
        }
    }

    float inv0 = 1.0f / l0;
    float inv1 = 1.0f / l1;
    int rA = r0g + gid;
    int rB = rA + 8;
#pragma unroll
    for (int nd = 0; nd < 8; nd++) {
        int col = nd * 8 + 2 * tig;
        *(float2*)(O + ((size_t)(b * S_ + rA) * H_ + h) * HD_ + col) = make_float2(
            round_tf32f(oacc[nd][0] * inv0), round_tf32f(oacc[nd][1] * inv0));
        *(float2*)(O + ((size_t)(b * S_ + rB) * H_ + h) * HD_ + col) = make_float2(
            round_tf32f(oacc[nd][2] * inv1), round_tf32f(oacc[nd][3] * inv1));
    }
}

// ---------------------------------------------------------------------------
// Launch (5 launches)
// ---------------------------------------------------------------------------
extern "C" void kernel_launch(void* const* d_in, const int* in_sizes, int n_in,
                              void* d_out, int out_size) {
    const float* x = (const float*)d_in[0];
    const float* cosb = (const float*)d_in[1];
    const float* sinb = (const float*)d_in[2];
    const float* wq = (const float*)d_in[4];
    const float* wk = (const float*)d_in[5];
    const float* wv = (const float*)d_in[6];
    const float* wo = (const float*)d_in[7];
    float* out = (float*)d_out;

    float *qkv, *o, *xr, *w4;
    cudaGetSymbolAddress((void**)&qkv, g_qkv);
    cudaGetSymbolAddress((void**)&o, g_o);
    cudaGetSymbolAddress((void**)&xr, g_x);
    cudaGetSymbolAddress((void**)&w4, g_w4);
    float* wor = w4 + 3 * DIM_ * DIM_;

    const int K = DIM_;

    cudaFuncSetAttribute(gemm_tf32p, cudaFuncAttributeMaxDynamicSharedMemorySize,
                         GEMM_SMEM);

    int nx4 = (B_ * S_ * DIM_) / 4;
    int nw4all = DIM_ * DIM_;
    round_tf32_kernel<<<nx4 / 256, 256>>>(x, xr, nx4);
    round_w4_kernel<<<nw4all / 256, 256>>>(wq, wk, wv, wo, w4);

    dim3 qkv_grid(NQKV / 128, (B_ * S_) / 128);   // (24, 32)
    gemm_tf32p<<<qkv_grid, 256, GEMM_SMEM>>>(xr, w4, qkv, NQKV, K, 1, cosb, sinb);

    dim3 attn_grid(S_ / 128, H_, B_);
    flash_mma<<<attn_grid, 256>>>(qkv, o);

    dim3 out_grid(DIM_ / 128, (B_ * S_) / 128);   // (8, 32)
    gemm_tf32p<<<out_grid, 256, GEMM_SMEM>>>(o, wor, out, DIM_, K, 0, cosb, sinb);
}